// round 16
// baseline (speedup 1.0000x reference)
#include <cuda_runtime.h>
#include <cuda_fp16.h>
#include <cstdint>

#define Bb 256
#define Tt 256
#define Cc 384
#define Hh 64
#define BT (Bb*Tt)
#define Ncat 192
#define KCH 32
#define NCHUNK (Cc/KCH)        // 12
#define BCHUNK_U32 3072        // hi-only packed B frags per K-chunk

// Scratch
__device__ float    g_v[BT*Hh];          // V fp32 [row][h]
__device__ uint32_t g_qp[BT*32];         // Q fp16 pairs, attn-fragment layout
__device__ uint32_t g_kp[BT*32];         // K fp16 pairs, attn-fragment layout
__device__ uint32_t g_Bp[NCHUNK * BCHUNK_U32];

// pack two floats as fp16x2: low half = a, high half = b
__device__ __forceinline__ uint32_t pack_f16(float a, float b) {
    uint32_t r;
    asm("cvt.rn.f16x2.f32 %0, %1, %2;" : "=r"(r) : "f"(b), "f"(a));
    return r;
}

__device__ __forceinline__ uint32_t h2exp2_u32(uint32_t x) {
    uint32_t r;
    asm("ex2.approx.f16x2 %0, %1;" : "=r"(r) : "r"(x));
    return r;
}

__device__ __forceinline__ void mma_f16(float* c, const uint32_t* a, uint2 b) {
    asm volatile("mma.sync.aligned.m16n8k16.row.col.f32.f16.f16.f32 "
        "{%0,%1,%2,%3}, {%4,%5,%6,%7}, {%8,%9}, {%0,%1,%2,%3};"
        : "+f"(c[0]), "+f"(c[1]), "+f"(c[2]), "+f"(c[3])
        : "r"(a[0]), "r"(a[1]), "r"(a[2]), "r"(a[3]), "r"(b.x), "r"(b.y));
}

// ---------------------------------------------------------------------------
// Kernel 0: pack W into per-chunk fragment layout, fp16 (hi only). (unchanged)
// ---------------------------------------------------------------------------
__global__ void wprep_kernel(const float* __restrict__ Wq,
                             const float* __restrict__ Wk,
                             const float* __restrict__ Wv)
{
    const int gid = blockIdx.x * blockDim.x + threadIdx.x;
    if (gid >= NCHUNK * BCHUNK_U32) return;
    const int chunk = gid / BCHUNK_U32;
    const int t  = gid % BCHUNK_U32;
    const int j  = t >> 7;               // 24
    const int s  = (t >> 6) & 1;
    const int l  = (t >> 1) & 31;
    const int rr = t & 1;
    const int gr = l >> 2, ct = l & 3;
    const int n  = j * 8 + gr;
    const int k  = chunk * 32 + s * 16 + 2 * ct + rr * 8;
    const float* W = (n < 64) ? Wq : (n < 128) ? Wk : Wv;
    const int hc = n & 63;
    g_Bp[gid] = pack_f16(W[k * Hh + hc], W[(k + 1) * Hh + hc]);
}

// ---------------------------------------------------------------------------
// Kernel 1: projection via mma.sync fp16 single-pass. (unchanged from R15)
// ---------------------------------------------------------------------------
#define PSM_U32 (2*2048 + 2*BCHUNK_U32)   // 10240 u32 = 40 KB

extern __shared__ char dynsm[];

__device__ __forceinline__ void ldgA(const float* __restrict__ x, long rowbase,
                                     int c, int tid, float4 av[4]) {
    #pragma unroll
    for (int i = 0; i < 4; i++) {
        const int idx = tid + i * 256;
        const int row = idx >> 3, c4 = idx & 7;
        av[i] = *(const float4*)(x + (rowbase + row) * Cc + c * KCH + c4 * 4);
    }
}

__device__ __forceinline__ void stsA(uint32_t* abuf, int tid, const float4 av[4]) {
    #pragma unroll
    for (int i = 0; i < 4; i++) {
        const int idx = tid + i * 256;
        const int row = idx >> 3, c4 = idx & 7;
        const int k2 = c4 * 2;
        const int base_i = ((row >> 4) * 2 + (k2 >> 3)) * 128;
        const int r = ((row >> 3) & 1) + (((k2 >> 2) & 1) << 1);
        const int lane4 = ((row & 7) << 2) | (k2 & 3);
        const int off = base_i + lane4 * 4 + r;
        abuf[off]     = pack_f16(av[i].x, av[i].y);
        abuf[off + 4] = pack_f16(av[i].z, av[i].w);
    }
}

__device__ __forceinline__ void ldgB(int c, int tid, float4 bv[3]) {
    const float4* src = (const float4*)(g_Bp + c * BCHUNK_U32);
    #pragma unroll
    for (int i = 0; i < 3; i++) bv[i] = src[tid + i * 256];
}

__device__ __forceinline__ void stsB(uint32_t* bbuf, int tid, const float4 bv[3]) {
    float4* dst = (float4*)bbuf;
    #pragma unroll
    for (int i = 0; i < 3; i++) dst[tid + i * 256] = bv[i];
}

__global__ __launch_bounds__(256) void proj_kernel(const float* __restrict__ x)
{
    uint32_t* psm = (uint32_t*)dynsm;
    const int tid  = threadIdx.x;
    const long rowbase = (long)blockIdx.x * 128;
    const int warp = tid >> 5, lane = tid & 31;
    const int mw = warp & 3, nw = warp >> 2;
    const int gr = lane >> 2, ct = lane & 3;

    float acc[2][12][4];
    #pragma unroll
    for (int im = 0; im < 2; im++)
        #pragma unroll
        for (int j = 0; j < 12; j++)
            #pragma unroll
            for (int r = 0; r < 4; r++) acc[im][j][r] = 0.f;

    {
        float4 av[4], bv[3];
        ldgA(x, rowbase, 0, tid, av);
        ldgB(0, tid, bv);
        stsA(psm, tid, av);
        stsB(psm + 4096, tid, bv);
    }
    __syncthreads();

    for (int c = 0; c < NCHUNK; c++) {
        float4 av[4], bv[3];
        const bool more = (c + 1 < NCHUNK);
        if (more) {
            ldgA(x, rowbase, c + 1, tid, av);
            ldgB(c + 1, tid, bv);
        }

        const uint32_t* abuf = psm + (c & 1) * 2048;
        const uint32_t* bbuf = psm + 4096 + (c & 1) * BCHUNK_U32;

        #pragma unroll
        for (int s = 0; s < 2; s++) {
            uint32_t ah[2][4];
            #pragma unroll
            for (int im = 0; im < 2; im++) {
                const int base = ((mw * 2 + im) * 2 + s) * 128 + lane * 4;
                const uint4 vh = *(const uint4*)(abuf + base);
                ah[im][0] = vh.x; ah[im][1] = vh.y; ah[im][2] = vh.z; ah[im][3] = vh.w;
            }
            #pragma unroll
            for (int j = 0; j < 12; j++) {
                const int jj = nw * 12 + j;
                const uint32_t* bp = bbuf + (jj * 2 + s) * 64 + lane * 2;
                const uint2 bh = *(const uint2*)(bp);
                #pragma unroll
                for (int im = 0; im < 2; im++) {
                    mma_f16(acc[im][j], ah[im], bh);
                }
            }
        }

        if (more) {
            uint32_t* abn = psm + ((c + 1) & 1) * 2048;
            uint32_t* bbn = psm + 4096 + ((c + 1) & 1) * BCHUNK_U32;
            stsA(abn, tid, av);
            stsB(bbn, tid, bv);
        }
        __syncthreads();
    }

    // Epilogue: q,k -> fp16 pairs in paired fragment layout; v -> fp32.
    #pragma unroll
    for (int im = 0; im < 2; im++) {
        #pragma unroll
        for (int j = 0; j < 12; j++) {
            const int jj = nw * 12 + j;
            const int n0 = jj * 8 + 2 * ct;
            const long row0 = rowbase + mw * 32 + im * 16 + gr;
            if (n0 < 128) {
                uint32_t* dst = (n0 < 64) ? g_qp : g_kp;
                const int jv = jj & 7;
                const int pos = (jv >> 1) * 8 + ct * 2 + (jv & 1);
                dst[row0 * 32 + pos]       = pack_f16(acc[im][j][0], acc[im][j][1]);
                dst[(row0 + 8) * 32 + pos] = pack_f16(acc[im][j][2], acc[im][j][3]);
            } else {
                const int hc = n0 & 63;
                *(float2*)(g_v + row0 * Hh + hc)       = make_float2(acc[im][j][0], acc[im][j][1]);
                *(float2*)(g_v + (row0 + 8) * Hh + hc) = make_float2(acc[im][j][2], acc[im][j][3]);
            }
        }
    }
}

// ---------------------------------------------------------------------------
// Kernel 2: flash attention — 2 CTAs per batch, 128 threads (4 warps) each.
// CTA h of batch b owns strips {h*4+w, 15-(h*4+w)} per warp w: each warp
// does exactly 5 key-blocks. Smaller CTA -> ~19K regs/CTA -> 2-3 CTAs/SM,
// killing the 2-wave quantization of the 256-thread version.
// ---------------------------------------------------------------------------
#define SKB 0
#define SVB 9216
#define ASM_U32 (9216 + 64*132)   // 17664 u32 = 70656 B

__global__ __launch_bounds__(128) void attn_kernel(float* __restrict__ out)
{
    uint32_t* sm = (uint32_t*)dynsm;
    uint32_t* sk = sm + SKB;
    uint32_t* sv = sm + SVB;

    const int b   = blockIdx.x >> 1;
    const int hh  = blockIdx.x & 1;
    const int tid = threadIdx.x;

    // Stage K: [256][32] u32 -> [256][36] padded. 2048 uint4 / 128 thr.
    {
        const uint4* gk = (const uint4*)(g_kp + (size_t)b * 8192);
        #pragma unroll
        for (int i = 0; i < 16; i++) {
            const int idx = tid + i * 128;
            const int row = idx >> 3, c4 = (idx & 7) * 4;
            *(uint4*)(sk + row * 36 + c4) = gk[idx];
        }
    }
    // Stage V: transpose fp32 [key][h] -> fp16 pairs [h][paired-kp layout].
    {
        const float* gv = g_v + (size_t)b * Tt * Hh;
        const int h = tid & 63, g = tid >> 6;       // g in {0,1}
        #pragma unroll
        for (int gi = 0; gi < 2; gi++) {
            const int gg = g + gi * 2;              // regions {0..3}
            #pragma unroll
            for (int kk = 0; kk < 32; kk++) {
                const int kp = gg * 32 + kk;
                const float v0 = gv[(2 * kp) * Hh + h];
                const float v1 = gv[(2 * kp + 1) * Hh + h];
                const int ks = kk >> 3, ctv = kk & 3, rv = (kk >> 2) & 1;
                sv[h * 132 + gg * 32 + ks * 8 + ctv * 2 + rv] = pack_f16(v0, v1);
            }
        }
    }
    __syncthreads();

    const int w = tid >> 5, lane = tid & 31;        // w in 0..3
    const int gr = lane >> 2, ct = lane & 3;
    const float scale2 = rsqrtf((float)Cc) * 1.4426950408889634f;  // C^-0.5 * log2(e)

    const uint32_t* gq = g_qp + (size_t)b * 8192;
    const int sbase = hh * 4 + w;                   // strip index 0..7

    #pragma unroll
    for (int half = 0; half < 2; half++) {
        const int s = half ? (15 - sbase) : sbase;  // strips sum to 5 blocks
        const int row0 = s * 16 + gr;
        const int row1 = row0 + 8;

        uint32_t qf[16];
        #pragma unroll
        for (int ks = 0; ks < 4; ks++) {
            const uint2 u0 = *(const uint2*)(gq + row0 * 32 + ks * 8 + ct * 2);
            const uint2 u1 = *(const uint2*)(gq + row1 * 32 + ks * 8 + ct * 2);
            qf[ks*4+0] = u0.x; qf[ks*4+2] = u0.y;
            qf[ks*4+1] = u1.x; qf[ks*4+3] = u1.y;
        }

        float l0 = 0.f, l1 = 0.f;
        float o[8][4];
        #pragma unroll
        for (int n = 0; n < 8; n++)
            #pragma unroll
            for (int r = 0; r < 4; r++) o[n][r] = 0.f;

        const int nb = (s >> 2) + 1;
        for (int kb = 0; kb < nb; kb++) {
            const int j0 = kb * 64;

            // ---- S = Q K^T ----
            float sa[8][4];
            #pragma unroll
            for (int n = 0; n < 8; n++)
                #pragma unroll
                for (int r = 0; r < 4; r++) sa[n][r] = 0.f;

            #pragma unroll
            for (int ks = 0; ks < 4; ks++) {
                #pragma unroll
                for (int n = 0; n < 8; n++) {
                    const int key = j0 + 8 * n + gr;
                    const uint2 bh = *(const uint2*)(sk + key * 36 + ks * 8 + ct * 2);
                    mma_f16(sa[n], &qf[ks*4], bh);
                }
            }

            // ---- P = exp2(s*scale2) fp16x2; mask only on diagonal block ----
            uint32_t pex0[8], pex1[8];
            if (kb == nb - 1) {
                #pragma unroll
                for (int n = 0; n < 8; n++) {
                    const int key0 = j0 + 8 * n + 2 * ct;
                    const float a0 = (key0     <= row0) ? sa[n][0] * scale2 : -1e30f;
                    const float a1 = (key0 + 1 <= row0) ? sa[n][1] * scale2 : -1e30f;
                    const float a2 = (key0     <= row1) ? sa[n][2] * scale2 : -1e30f;
                    const float a3 = (key0 + 1 <= row1) ? sa[n][3] * scale2 : -1e30f;
                    pex0[n] = h2exp2_u32(pack_f16(a0, a1));   // -inf -> 0
                    pex1[n] = h2exp2_u32(pack_f16(a2, a3));
                }
            } else {
                #pragma unroll
                for (int n = 0; n < 8; n++) {
                    pex0[n] = h2exp2_u32(pack_f16(sa[n][0] * scale2, sa[n][1] * scale2));
                    pex1[n] = h2exp2_u32(pack_f16(sa[n][2] * scale2, sa[n][3] * scale2));
                }
            }

            // ---- l accumulation (fp32, off critical path) ----
            #pragma unroll
            for (int n = 0; n < 8; n++) {
                __half2 h0 = *reinterpret_cast<__half2*>(&pex0[n]);
                __half2 h1 = *reinterpret_cast<__half2*>(&pex1[n]);
                const float2 f0 = __half22float2(h0);
                const float2 f1 = __half22float2(h1);
                l0 += f0.x + f0.y;
                l1 += f1.x + f1.y;
            }

            // ---- O += P V ----
            #pragma unroll
            for (int ks = 0; ks < 4; ks++) {
                uint32_t ph[4];
                ph[0] = pex0[2*ks];   ph[1] = pex1[2*ks];
                ph[2] = pex0[2*ks+1]; ph[3] = pex1[2*ks+1];
                const int kb2 = (j0 >> 1) + ks * 8 + ct * 2;
                #pragma unroll
                for (int hn = 0; hn < 8; hn++) {
                    const uint2 vb = *(const uint2*)(sv + (hn * 8 + gr) * 132 + kb2);
                    mma_f16(o[hn], ph, vb);
                }
            }
        }

        // ---- finalize: quad-reduce l over key columns, normalize, store ----
        l0 += __shfl_xor_sync(0xffffffffu, l0, 1);
        l0 += __shfl_xor_sync(0xffffffffu, l0, 2);
        l1 += __shfl_xor_sync(0xffffffffu, l1, 1);
        l1 += __shfl_xor_sync(0xffffffffu, l1, 2);
        const float inv0 = 1.0f / l0, inv1 = 1.0f / l1;

        #pragma unroll
        for (int hn = 0; hn < 8; hn++) {
            const int hc = hn * 8 + 2 * ct;
            *(float2*)(out + ((size_t)(b * 256 + row0)) * Hh + hc) =
                make_float2(o[hn][0] * inv0, o[hn][1] * inv0);
            *(float2*)(out + ((size_t)(b * 256 + row1)) * Hh + hc) =
                make_float2(o[hn][2] * inv1, o[hn][3] * inv1);
        }
    }
}

// ---------------------------------------------------------------------------
// Launch
// ---------------------------------------------------------------------------
extern "C" void kernel_launch(void* const* d_in, const int* in_sizes, int n_in,
                              void* d_out, int out_size)
{
    const float* x  = (const float*)d_in[0];
    const float* Wq = (const float*)d_in[1];
    const float* Wk = (const float*)d_in[2];
    const float* Wv = (const float*)d_in[3];
    float* out = (float*)d_out;

    (void)in_sizes; (void)n_in; (void)out_size;

    const int proj_smem = PSM_U32 * 4;      // 40 KB
    const int attn_smem = ASM_U32 * 4;      // ~69 KB
    cudaFuncSetAttribute(proj_kernel,
                         cudaFuncAttributeMaxDynamicSharedMemorySize, proj_smem);
    cudaFuncSetAttribute(attn_kernel,
                         cudaFuncAttributeMaxDynamicSharedMemorySize, attn_smem);

    wprep_kernel<<<(NCHUNK * BCHUNK_U32 + 255) / 256, 256>>>(Wq, Wk, Wv);
    proj_kernel<<<BT / 128, 256, proj_smem>>>(x);
    attn_kernel<<<2 * Bb, 128, attn_smem>>>(out);
}

// round 17
// speedup vs baseline: 1.0480x; 1.0480x over previous
#include <cuda_runtime.h>
#include <cuda_fp16.h>
#include <cstdint>

#define Bb 256
#define Tt 256
#define Cc 384
#define Hh 64
#define BT (Bb*Tt)
#define Ncat 192
#define KCH 32
#define NCHUNK (Cc/KCH)        // 12
#define BCHUNK_U32 3072        // hi-only packed B frags per K-chunk

// Scratch
__device__ uint32_t g_qp[BT*32];         // Q fp16 pairs, attn-fragment layout
__device__ uint32_t g_kp[BT*32];         // K fp16 pairs, attn-fragment layout
__device__ uint32_t g_vt[Bb*Hh*128];     // V fp16 key-pairs, [batch][h][paired-kp]
__device__ uint32_t g_Bp[NCHUNK * BCHUNK_U32];

// pack two floats as fp16x2: low half = a, high half = b
__device__ __forceinline__ uint32_t pack_f16(float a, float b) {
    uint32_t r;
    asm("cvt.rn.f16x2.f32 %0, %1, %2;" : "=r"(r) : "f"(b), "f"(a));
    return r;
}

__device__ __forceinline__ uint32_t h2exp2_u32(uint32_t x) {
    uint32_t r;
    asm("ex2.approx.f16x2 %0, %1;" : "=r"(r) : "r"(x));
    return r;
}

__device__ __forceinline__ void mma_f16(float* c, const uint32_t* a, uint2 b) {
    asm volatile("mma.sync.aligned.m16n8k16.row.col.f32.f16.f16.f32 "
        "{%0,%1,%2,%3}, {%4,%5,%6,%7}, {%8,%9}, {%0,%1,%2,%3};"
        : "+f"(c[0]), "+f"(c[1]), "+f"(c[2]), "+f"(c[3])
        : "r"(a[0]), "r"(a[1]), "r"(a[2]), "r"(a[3]), "r"(b.x), "r"(b.y));
}

// ---------------------------------------------------------------------------
// Kernel 0: pack W into per-chunk fragment layout, fp16 (hi only). (unchanged)
// ---------------------------------------------------------------------------
__global__ void wprep_kernel(const float* __restrict__ Wq,
                             const float* __restrict__ Wk,
                             const float* __restrict__ Wv)
{
    const int gid = blockIdx.x * blockDim.x + threadIdx.x;
    if (gid >= NCHUNK * BCHUNK_U32) return;
    const int chunk = gid / BCHUNK_U32;
    const int t  = gid % BCHUNK_U32;
    const int j  = t >> 7;               // 24
    const int s  = (t >> 6) & 1;
    const int l  = (t >> 1) & 31;
    const int rr = t & 1;
    const int gr = l >> 2, ct = l & 3;
    const int n  = j * 8 + gr;
    const int k  = chunk * 32 + s * 16 + 2 * ct + rr * 8;
    const float* W = (n < 64) ? Wq : (n < 128) ? Wk : Wv;
    const int hc = n & 63;
    g_Bp[gid] = pack_f16(W[k * Hh + hc], W[(k + 1) * Hh + hc]);
}

// ---------------------------------------------------------------------------
// Kernel 1: projection via mma.sync fp16 single-pass. Epilogue now also
// transposes V through smem and writes g_vt in attn's fp16 paired layout.
// ---------------------------------------------------------------------------
#define PSM_U32 (2*2048 + 2*BCHUNK_U32)   // 10240 u32 = 40 KB

extern __shared__ char dynsm[];

__device__ __forceinline__ void ldgA(const float* __restrict__ x, long rowbase,
                                     int c, int tid, float4 av[4]) {
    #pragma unroll
    for (int i = 0; i < 4; i++) {
        const int idx = tid + i * 256;
        const int row = idx >> 3, c4 = idx & 7;
        av[i] = *(const float4*)(x + (rowbase + row) * Cc + c * KCH + c4 * 4);
    }
}

__device__ __forceinline__ void stsA(uint32_t* abuf, int tid, const float4 av[4]) {
    #pragma unroll
    for (int i = 0; i < 4; i++) {
        const int idx = tid + i * 256;
        const int row = idx >> 3, c4 = idx & 7;
        const int k2 = c4 * 2;
        const int base_i = ((row >> 4) * 2 + (k2 >> 3)) * 128;
        const int r = ((row >> 3) & 1) + (((k2 >> 2) & 1) << 1);
        const int lane4 = ((row & 7) << 2) | (k2 & 3);
        const int off = base_i + lane4 * 4 + r;
        abuf[off]     = pack_f16(av[i].x, av[i].y);
        abuf[off + 4] = pack_f16(av[i].z, av[i].w);
    }
}

__device__ __forceinline__ void ldgB(int c, int tid, float4 bv[3]) {
    const float4* src = (const float4*)(g_Bp + c * BCHUNK_U32);
    #pragma unroll
    for (int i = 0; i < 3; i++) bv[i] = src[tid + i * 256];
}

__device__ __forceinline__ void stsB(uint32_t* bbuf, int tid, const float4 bv[3]) {
    float4* dst = (float4*)bbuf;
    #pragma unroll
    for (int i = 0; i < 3; i++) dst[tid + i * 256] = bv[i];
}

__global__ __launch_bounds__(256) void proj_kernel(const float* __restrict__ x)
{
    uint32_t* psm = (uint32_t*)dynsm;
    const int tid  = threadIdx.x;
    const long rowbase = (long)blockIdx.x * 128;
    const int warp = tid >> 5, lane = tid & 31;
    const int mw = warp & 3, nw = warp >> 2;
    const int gr = lane >> 2, ct = lane & 3;

    float acc[2][12][4];
    #pragma unroll
    for (int im = 0; im < 2; im++)
        #pragma unroll
        for (int j = 0; j < 12; j++)
            #pragma unroll
            for (int r = 0; r < 4; r++) acc[im][j][r] = 0.f;

    {
        float4 av[4], bv[3];
        ldgA(x, rowbase, 0, tid, av);
        ldgB(0, tid, bv);
        stsA(psm, tid, av);
        stsB(psm + 4096, tid, bv);
    }
    __syncthreads();

    for (int c = 0; c < NCHUNK; c++) {
        float4 av[4], bv[3];
        const bool more = (c + 1 < NCHUNK);
        if (more) {
            ldgA(x, rowbase, c + 1, tid, av);
            ldgB(c + 1, tid, bv);
        }

        const uint32_t* abuf = psm + (c & 1) * 2048;
        const uint32_t* bbuf = psm + 4096 + (c & 1) * BCHUNK_U32;

        #pragma unroll
        for (int s = 0; s < 2; s++) {
            uint32_t ah[2][4];
            #pragma unroll
            for (int im = 0; im < 2; im++) {
                const int base = ((mw * 2 + im) * 2 + s) * 128 + lane * 4;
                const uint4 vh = *(const uint4*)(abuf + base);
                ah[im][0] = vh.x; ah[im][1] = vh.y; ah[im][2] = vh.z; ah[im][3] = vh.w;
            }
            #pragma unroll
            for (int j = 0; j < 12; j++) {
                const int jj = nw * 12 + j;
                const uint32_t* bp = bbuf + (jj * 2 + s) * 64 + lane * 2;
                const uint2 bh = *(const uint2*)(bp);
                #pragma unroll
                for (int im = 0; im < 2; im++) {
                    mma_f16(acc[im][j], ah[im], bh);
                }
            }
        }

        if (more) {
            uint32_t* abn = psm + ((c + 1) & 1) * 2048;
            uint32_t* bbn = psm + 4096 + ((c + 1) & 1) * BCHUNK_U32;
            stsA(abn, tid, av);
            stsB(bbn, tid, bv);
        }
        __syncthreads();
    }

    // Epilogue part 1: q,k -> gmem fp16 pairs; V -> smem bounce (fp16 h-pairs).
    // vbuf (reuses psm): [row(128)][33 padded], u32 = pack(V[row][hc],V[row][hc+1])
    #pragma unroll
    for (int im = 0; im < 2; im++) {
        #pragma unroll
        for (int j = 0; j < 12; j++) {
            const int jj = nw * 12 + j;
            const int n0 = jj * 8 + 2 * ct;
            const long row0 = rowbase + mw * 32 + im * 16 + gr;
            if (n0 < 128) {
                uint32_t* dst = (n0 < 64) ? g_qp : g_kp;
                const int jv = jj & 7;
                const int pos = (jv >> 1) * 8 + ct * 2 + (jv & 1);
                dst[row0 * 32 + pos]       = pack_f16(acc[im][j][0], acc[im][j][1]);
                dst[(row0 + 8) * 32 + pos] = pack_f16(acc[im][j][2], acc[im][j][3]);
            } else {
                const int lrow = mw * 32 + im * 16 + gr;       // local row 0..127
                const int hcol2 = (jj & 7) * 4 + ct;           // (hc>>1), 0..31
                psm[lrow * 33 + hcol2]       = pack_f16(acc[im][j][0], acc[im][j][1]);
                psm[(lrow + 8) * 33 + hcol2] = pack_f16(acc[im][j][2], acc[im][j][3]);
            }
        }
    }
    __syncthreads();

    // Epilogue part 2: re-pair V across rows -> g_vt[batch][h][paired-kp pos].
    {
        const int batch  = blockIdx.x >> 1;
        const int ggbase = (blockIdx.x & 1) * 2;     // this CTA covers 2 kp-regions
        const __half* vh = (const __half*)psm;       // half idx = row*66 + h
        #pragma unroll
        for (int i = 0; i < 16; i++) {               // 4096 pair-entries / 256 thr
            const int idx = tid + i * 256;
            const int kpl = idx & 63;                // local key-pair 0..63
            const int h   = idx >> 6;                // 0..63
            const __half v0 = vh[(2 * kpl) * 66 + h];
            const __half v1 = vh[(2 * kpl + 1) * 66 + h];
            const uint32_t u = (uint32_t)__half_as_ushort(v0)
                             | ((uint32_t)__half_as_ushort(v1) << 16);
            const int gg = ggbase + (kpl >> 5);
            const int kk = kpl & 31;
            const int ks = kk >> 3, ctv = kk & 3, rv = (kk >> 2) & 1;
            g_vt[(size_t)batch * 8192 + h * 128 + gg * 32 + ks * 8 + ctv * 2 + rv] = u;
        }
    }
}

// ---------------------------------------------------------------------------
// Kernel 2: flash attention (R15 structure: 256 thr, strip-skipping, no-max
// softmax). V staging is now a plain coalesced copy from g_vt.
// ---------------------------------------------------------------------------
#define SKB 0
#define SVB 9216
#define ASM_U32 (9216 + 64*132)   // 17664 u32 = 70656 B

__global__ __launch_bounds__(256) void attn_kernel(float* __restrict__ out)
{
    uint32_t* sm = (uint32_t*)dynsm;
    uint32_t* sk = sm + SKB;
    uint32_t* sv = sm + SVB;

    const int b   = blockIdx.x;
    const int tid = threadIdx.x;

    // Stage K: [256][32] u32 -> [256][36] padded.
    {
        const uint4* gk = (const uint4*)(g_kp + (size_t)b * 8192);
        #pragma unroll
        for (int i = 0; i < 8; i++) {
            const int idx = tid + i * 256;
            const int row = idx >> 3, c4 = (idx & 7) * 4;
            *(uint4*)(sk + row * 36 + c4) = gk[idx];
        }
    }
    // Stage V: plain copy [64][128] -> [64][132] padded.
    {
        const uint4* gv = (const uint4*)(g_vt + (size_t)b * 8192);
        #pragma unroll
        for (int i = 0; i < 8; i++) {
            const int idx = tid + i * 256;           // 2048 uint4
            const int h = idx >> 5, c4 = (idx & 31) * 4;
            *(uint4*)(sv + h * 132 + c4) = gv[idx];
        }
    }
    __syncthreads();

    const int w = tid >> 5, lane = tid & 31;
    const int gr = lane >> 2, ct = lane & 3;
    const float scale2 = rsqrtf((float)Cc) * 1.4426950408889634f;  // C^-0.5 * log2(e)

    const uint32_t* gq = g_qp + (size_t)b * 8192;

    #pragma unroll
    for (int half = 0; half < 2; half++) {
        const int s = half ? (15 - w) : w;       // strip index 0..15
        const int row0 = s * 16 + gr;
        const int row1 = row0 + 8;

        uint32_t qf[16];
        #pragma unroll
        for (int ks = 0; ks < 4; ks++) {
            const uint2 u0 = *(const uint2*)(gq + row0 * 32 + ks * 8 + ct * 2);
            const uint2 u1 = *(const uint2*)(gq + row1 * 32 + ks * 8 + ct * 2);
            qf[ks*4+0] = u0.x; qf[ks*4+2] = u0.y;
            qf[ks*4+1] = u1.x; qf[ks*4+3] = u1.y;
        }

        float l0 = 0.f, l1 = 0.f;
        float o[8][4];
        #pragma unroll
        for (int n = 0; n < 8; n++)
            #pragma unroll
            for (int r = 0; r < 4; r++) o[n][r] = 0.f;

        const int nb = (s >> 2) + 1;             // blocks needed by this strip
        for (int kb = 0; kb < nb; kb++) {
            const int j0 = kb * 64;

            // ---- S = Q K^T ----
            float sa[8][4];
            #pragma unroll
            for (int n = 0; n < 8; n++)
                #pragma unroll
                for (int r = 0; r < 4; r++) sa[n][r] = 0.f;

            #pragma unroll
            for (int ks = 0; ks < 4; ks++) {
                #pragma unroll
                for (int n = 0; n < 8; n++) {
                    const int key = j0 + 8 * n + gr;
                    const uint2 bh = *(const uint2*)(sk + key * 36 + ks * 8 + ct * 2);
                    mma_f16(sa[n], &qf[ks*4], bh);
                }
            }

            // ---- P = exp2(s*scale2) fp16x2; mask only on diagonal block ----
            uint32_t pex0[8], pex1[8];
            if (kb == nb - 1) {
                #pragma unroll
                for (int n = 0; n < 8; n++) {
                    const int key0 = j0 + 8 * n + 2 * ct;
                    const float a0 = (key0     <= row0) ? sa[n][0] * scale2 : -1e30f;
                    const float a1 = (key0 + 1 <= row0) ? sa[n][1] * scale2 : -1e30f;
                    const float a2 = (key0     <= row1) ? sa[n][2] * scale2 : -1e30f;
                    const float a3 = (key0 + 1 <= row1) ? sa[n][3] * scale2 : -1e30f;
                    pex0[n] = h2exp2_u32(pack_f16(a0, a1));   // -inf -> 0
                    pex1[n] = h2exp2_u32(pack_f16(a2, a3));
                }
            } else {
                #pragma unroll
                for (int n = 0; n < 8; n++) {
                    pex0[n] = h2exp2_u32(pack_f16(sa[n][0] * scale2, sa[n][1] * scale2));
                    pex1[n] = h2exp2_u32(pack_f16(sa[n][2] * scale2, sa[n][3] * scale2));
                }
            }

            // ---- l accumulation (fp32, off critical path) ----
            #pragma unroll
            for (int n = 0; n < 8; n++) {
                __half2 h0 = *reinterpret_cast<__half2*>(&pex0[n]);
                __half2 h1 = *reinterpret_cast<__half2*>(&pex1[n]);
                const float2 f0 = __half22float2(h0);
                const float2 f1 = __half22float2(h1);
                l0 += f0.x + f0.y;
                l1 += f1.x + f1.y;
            }

            // ---- O += P V ----
            #pragma unroll
            for (int ks = 0; ks < 4; ks++) {
                uint32_t ph[4];
                ph[0] = pex0[2*ks];   ph[1] = pex1[2*ks];
                ph[2] = pex0[2*ks+1]; ph[3] = pex1[2*ks+1];
                const int kb2 = (j0 >> 1) + ks * 8 + ct * 2;
                #pragma unroll
                for (int hn = 0; hn < 8; hn++) {
                    const uint2 vb = *(const uint2*)(sv + (hn * 8 + gr) * 132 + kb2);
                    mma_f16(o[hn], ph, vb);
                }
            }
        }

        // ---- finalize: quad-reduce l over key columns, normalize, store ----
        l0 += __shfl_xor_sync(0xffffffffu, l0, 1);
        l0 += __shfl_xor_sync(0xffffffffu, l0, 2);
        l1 += __shfl_xor_sync(0xffffffffu, l1, 1);
        l1 += __shfl_xor_sync(0xffffffffu, l1, 2);
        const float inv0 = 1.0f / l0, inv1 = 1.0f / l1;

        #pragma unroll
        for (int hn = 0; hn < 8; hn++) {
            const int hc = hn * 8 + 2 * ct;
            *(float2*)(out + ((size_t)(b * 256 + row0)) * Hh + hc) =
                make_float2(o[hn][0] * inv0, o[hn][1] * inv0);
            *(float2*)(out + ((size_t)(b * 256 + row1)) * Hh + hc) =
                make_float2(o[hn][2] * inv1, o[hn][3] * inv1);
        }
    }
}

// ---------------------------------------------------------------------------
// Launch
// ---------------------------------------------------------------------------
extern "C" void kernel_launch(void* const* d_in, const int* in_sizes, int n_in,
                              void* d_out, int out_size)
{
    const float* x  = (const float*)d_in[0];
    const float* Wq = (const float*)d_in[1];
    const float* Wk = (const float*)d_in[2];
    const float* Wv = (const float*)d_in[3];
    float* out = (float*)d_out;

    (void)in_sizes; (void)n_in; (void)out_size;

    const int proj_smem = PSM_U32 * 4;      // 40 KB
    const int attn_smem = ASM_U32 * 4;      // ~69 KB
    cudaFuncSetAttribute(proj_kernel,
                         cudaFuncAttributeMaxDynamicSharedMemorySize, proj_smem);
    cudaFuncSetAttribute(attn_kernel,
                         cudaFuncAttributeMaxDynamicSharedMemorySize, attn_smem);

    wprep_kernel<<<(NCHUNK * BCHUNK_U32 + 255) / 256, 256>>>(Wq, Wk, Wv);
    proj_kernel<<<BT / 128, 256, proj_smem>>>(x);
    attn_kernel<<<Bb, 256, attn_smem>>>(out);
}